// round 15
// baseline (speedup 1.0000x reference)
#include <cuda_runtime.h>
#include <math.h>

#define B_    256
#define S_    512
#define E_    256
#define H_    512
#define G3_   1536      // 3*H
#define VOCAB_ 32000

// ---------------- device scratch (no allocation allowed) ----------------
__device__ float d_VW[(size_t)VOCAB_ * G3_]; // emb @ Wx^T + b_ih  (196.6 MB)
__device__ float d_WxT [E_ * G3_];           // [k][g*512+u]  (w_ih_w cols 0..255)
__device__ float d_WhT [H_ * G3_];           // w_ih_w cols 256..767 transposed
__device__ float d_WhhT[H_ * G3_];           // w_hh_w transposed
__device__ float d_WipT[H_ * G3_];           // w_ih_p transposed
__device__ float d_WhpT[H_ * G3_];           // w_hh_p transposed
__device__ float d_pinT[H_ * H_];            // pin_w transposed [k][c]
__device__ float d_fusT[2 * H_ * H_];        // fus_w transposed
__device__ float d_h1T [H_ * H_];            // h1_w transposed
__device__ float d_hw[2][B_ * H_];           // worker hidden (permuted), double buffered
__device__ float d_hp[2][B_ * H_];           // planner hidden (permuted), double buffered
__device__ float d_HPP[B_ * G3_];            // hp @ WhT (permuted)
__device__ float d_pi [B_ * H_];             // planner input projection (permuted)
__device__ float d_fused[B_ * H_];
__device__ float d_relu [B_ * H_];
__device__ int   d_perm[B_];                 // sorted-rank -> original batch index
__device__ int   d_lens_s[B_];               // lengths sorted descending

// ---------------- math helpers ----------------
__device__ __forceinline__ float sigf(float x) {
    return 1.0f / (1.0f + __expf(-x));
}
__device__ __forceinline__ float tanh_fast(float x) {
    float ax = fabsf(x);
    float e  = __expf(-2.0f * ax);
    float t  = (1.0f - e) / (1.0f + e);
    return copysignf(t, x);
}
__device__ __forceinline__ unsigned long long pack2s(float v) {
    unsigned long long r;
    asm("mov.b64 %0, {%1, %1};" : "=l"(r) : "f"(v));
    return r;
}
__device__ __forceinline__ float2 unpack2(unsigned long long v) {
    float2 f;
    asm("mov.b64 {%0, %1}, %2;" : "=f"(f.x), "=f"(f.y) : "l"(v));
    return f;
}
__device__ __forceinline__ void ffma2(unsigned long long &d,
                                      unsigned long long a, unsigned long long b) {
    asm("fma.rn.f32x2 %0, %1, %2, %0;" : "+l"(d) : "l"(a), "l"(b));
}
__device__ __forceinline__ void cp16(float* smem_dst, const float* gmem_src) {
    unsigned s = (unsigned)__cvta_generic_to_shared(smem_dst);
    asm volatile("cp.async.cg.shared.global [%0], [%1], 16;\n" :: "r"(s), "l"(gmem_src));
}
#define CP_COMMIT() asm volatile("cp.async.commit_group;\n" ::)
#define CP_WAIT0()  asm volatile("cp.async.wait_group 0;\n" ::)

__device__ __forceinline__ void unpack8(const unsigned long long a[4], float o[8]) {
    #pragma unroll
    for (int p = 0; p < 4; p++) {
        float2 v = unpack2(a[p]);
        o[2 * p]     = v.x;
        o[2 * p + 1] = v.y;
    }
}

// ---------------- init ----------------
__global__ void init_zero_kernel() {
    int i = blockIdx.x * blockDim.x + threadIdx.x;
    if (i < B_ * H_) { d_hw[0][i] = 0.0f; d_hp[0][i] = 0.0f; }
    if (i < B_ * G3_) d_HPP[i] = 0.0f;
}

// ---------------- sort batch rows by descending length (deterministic) ----------------
__global__ void sort_kernel(const int* __restrict__ lens) {
    __shared__ int L[B_];
    int i = threadIdx.x;
    L[i] = lens[i];
    __syncthreads();
    int li = L[i];
    int rank = 0;
    for (int j = 0; j < B_; j++) {
        int lj = L[j];
        if (lj > li || (lj == li && j < i)) rank++;
    }
    d_perm[rank]   = i;
    d_lens_s[rank] = li;
}

// ---------------- transpose all weight matrices ----------------
__global__ void transpose_all_kernel(
    const float* __restrict__ wihw, const float* __restrict__ whhw,
    const float* __restrict__ wihp, const float* __restrict__ whhp,
    const float* __restrict__ pinw, const float* __restrict__ fusw,
    const float* __restrict__ h1w)
{
    const float* src; float* dst; int R, K, ld, coff;
    switch (blockIdx.z) {
        case 0: src=wihw; dst=d_WxT;  R=G3_; K=E_;    ld=E_+H_; coff=0;   break;
        case 1: src=wihw; dst=d_WhT;  R=G3_; K=H_;    ld=E_+H_; coff=E_;  break;
        case 2: src=whhw; dst=d_WhhT; R=G3_; K=H_;    ld=H_;    coff=0;   break;
        case 3: src=wihp; dst=d_WipT; R=G3_; K=H_;    ld=H_;    coff=0;   break;
        case 4: src=whhp; dst=d_WhpT; R=G3_; K=H_;    ld=H_;    coff=0;   break;
        case 5: src=pinw; dst=d_pinT; R=H_;  K=H_;    ld=H_;    coff=0;   break;
        case 6: src=fusw; dst=d_fusT; R=H_;  K=2*H_;  ld=2*H_;  coff=0;   break;
        default:src=h1w;  dst=d_h1T;  R=H_;  K=H_;    ld=H_;    coff=0;   break;
    }
    __shared__ float tile[32][33];
    int r0 = blockIdx.y * 32, k0 = blockIdx.x * 32;
    int r = r0 + threadIdx.y, k = k0 + threadIdx.x;
    if (r < R && k < K) tile[threadIdx.y][threadIdx.x] = src[r * ld + coff + k];
    __syncthreads();
    int rr = r0 + threadIdx.x, kk = k0 + threadIdx.y;
    if (rr < R && kk < K) dst[(size_t)kk * R + rr] = tile[threadIdx.x][threadIdx.y];
}

// ======================= GEMM v3: lane = unit, warp = 8 rows =======================
// Block = 128 threads (4 warps). Tile 32 rows x 32 units (x3 gates for gemm3).
// A staged via regs->smem transpose As[k][m] (stride 32, conflict-free stores:
// every STS has all lanes at the same k with distinct m).
// B staged via cp.async, Bs[k][g*32+u] (stride 96): reads are full-efficiency
// 32-bank LDS.32. A reads are 2 broadcast LDS.128 (4 row-pairs as f32x2).
// Per warp per k: 2 LDS.128 + 3 LDS.32 + 3 mov + 12 FFMA2 -> fma-bound.
#define AS_T 1024   // 32k * 32m floats per buffer
#define BS3T 3072   // 32k * 96 floats per buffer
#define BS1T 1024   // 32k * 32 floats per buffer

__device__ __forceinline__ void gemm3v3(
    const float* __restrict__ A, int lda,
    const float* __restrict__ BT, int K,
    int m0, int u0,
    unsigned long long acc[3][4],
    float* __restrict__ As /*2*AS_T*/, float* __restrict__ Bs /*2*BS3T*/)
{
    const int tid  = threadIdx.x;
    const int lane = tid & 31;
    const int w    = tid >> 5;           // warp 0..3
    const int am   = lane;               // A loader: row
    const int ak   = w << 3;             // A loader: k-range base (8 k per warp)
    const int NT   = K >> 5;
    const float* Arow = A + (size_t)(m0 + am) * lda + ak;

    float4 av0, av1;
    // prologue: A(tile0) -> regs, B(tile0) -> cp.async
    av0 = *(const float4*)(Arow);
    av1 = *(const float4*)(Arow + 4);
    #pragma unroll
    for (int jj = 0; jj < 6; jj++) {
        int e = (tid + (jj << 7)) << 2;     // float offset 0..3068
        int k = e / 96, c = e % 96;
        cp16(Bs + k * 96 + c,
             BT + (size_t)k * G3_ + (c >> 5) * H_ + u0 + (c & 31));
    }
    CP_COMMIT();
    {   // store A(tile0) into buf0
        float* d = As;
        d[(ak + 0) * 32 + am] = av0.x; d[(ak + 1) * 32 + am] = av0.y;
        d[(ak + 2) * 32 + am] = av0.z; d[(ak + 3) * 32 + am] = av0.w;
        d[(ak + 4) * 32 + am] = av1.x; d[(ak + 5) * 32 + am] = av1.y;
        d[(ak + 6) * 32 + am] = av1.z; d[(ak + 7) * 32 + am] = av1.w;
    }
    if (NT > 1) {   // A(tile1) -> regs
        av0 = *(const float4*)(Arow + 32);
        av1 = *(const float4*)(Arow + 36);
    }
    CP_WAIT0();
    __syncthreads();

    for (int t = 0; t < NT; t++) {
        const int cb = t & 1, nb = (t + 1) & 1;
        if (t + 1 < NT) {
            int k0 = (t + 1) << 5;
            #pragma unroll
            for (int jj = 0; jj < 6; jj++) {
                int e = (tid + (jj << 7)) << 2;
                int k = e / 96, c = e % 96;
                cp16(Bs + nb * BS3T + k * 96 + c,
                     BT + (size_t)(k0 + k) * G3_ + (c >> 5) * H_ + u0 + (c & 31));
            }
            CP_COMMIT();
            float* d = As + nb * AS_T;   // safe: last readers of nb finished before entry sync
            d[(ak + 0) * 32 + am] = av0.x; d[(ak + 1) * 32 + am] = av0.y;
            d[(ak + 2) * 32 + am] = av0.z; d[(ak + 3) * 32 + am] = av0.w;
            d[(ak + 4) * 32 + am] = av1.x; d[(ak + 5) * 32 + am] = av1.y;
            d[(ak + 6) * 32 + am] = av1.z; d[(ak + 7) * 32 + am] = av1.w;
            if (t + 2 < NT) {
                const float* p = Arow + ((t + 2) << 5);
                av0 = *(const float4*)(p);
                av1 = *(const float4*)(p + 4);
            }
        }
        const float* Ab = As + cb * AS_T;
        const float* Bb = Bs + cb * BS3T;
        #pragma unroll
        for (int k = 0; k < 32; k++) {
            double2 aL = *(const double2*)(Ab + k * 32 + (w << 3));      // rows w8+0..3
            double2 aH = *(const double2*)(Ab + k * 32 + (w << 3) + 4);  // rows w8+4..7
            unsigned long long a0 = __double_as_longlong(aL.x);
            unsigned long long a1 = __double_as_longlong(aL.y);
            unsigned long long a2 = __double_as_longlong(aH.x);
            unsigned long long a3 = __double_as_longlong(aH.y);
            unsigned long long br = pack2s(Bb[k * 96 + lane]);
            unsigned long long bz = pack2s(Bb[k * 96 + 32 + lane]);
            unsigned long long bn = pack2s(Bb[k * 96 + 64 + lane]);
            ffma2(acc[0][0], a0, br); ffma2(acc[0][1], a1, br);
            ffma2(acc[0][2], a2, br); ffma2(acc[0][3], a3, br);
            ffma2(acc[1][0], a0, bz); ffma2(acc[1][1], a1, bz);
            ffma2(acc[1][2], a2, bz); ffma2(acc[1][3], a3, bz);
            ffma2(acc[2][0], a0, bn); ffma2(acc[2][1], a1, bn);
            ffma2(acc[2][2], a2, bn); ffma2(acc[2][3], a3, bn);
        }
        CP_WAIT0();
        __syncthreads();
    }
}

// single-gate variant: BT row stride ldb, tile 32x32
__device__ __forceinline__ void gemm1v3(
    const float* __restrict__ A, int lda,
    const float* __restrict__ BT, int ldb, int K,
    int m0, int u0,
    unsigned long long acc[4],
    float* __restrict__ As /*2*AS_T*/, float* __restrict__ Bs /*2*BS1T*/)
{
    const int tid  = threadIdx.x;
    const int lane = tid & 31;
    const int w    = tid >> 5;
    const int am   = lane;
    const int ak   = w << 3;
    const int NT   = K >> 5;
    const float* Arow = A + (size_t)(m0 + am) * lda + ak;

    float4 av0, av1;
    av0 = *(const float4*)(Arow);
    av1 = *(const float4*)(Arow + 4);
    #pragma unroll
    for (int jj = 0; jj < 2; jj++) {
        int e = (tid + (jj << 7)) << 2;     // 0..1020
        int k = e >> 5, c = e & 31;
        cp16(Bs + k * 32 + c, BT + (size_t)k * ldb + u0 + c);
    }
    CP_COMMIT();
    {
        float* d = As;
        d[(ak + 0) * 32 + am] = av0.x; d[(ak + 1) * 32 + am] = av0.y;
        d[(ak + 2) * 32 + am] = av0.z; d[(ak + 3) * 32 + am] = av0.w;
        d[(ak + 4) * 32 + am] = av1.x; d[(ak + 5) * 32 + am] = av1.y;
        d[(ak + 6) * 32 + am] = av1.z; d[(ak + 7) * 32 + am] = av1.w;
    }
    if (NT > 1) {
        av0 = *(const float4*)(Arow + 32);
        av1 = *(const float4*)(Arow + 36);
    }
    CP_WAIT0();
    __syncthreads();

    for (int t = 0; t < NT; t++) {
        const int cb = t & 1, nb = (t + 1) & 1;
        if (t + 1 < NT) {
            int k0 = (t + 1) << 5;
            #pragma unroll
            for (int jj = 0; jj < 2; jj++) {
                int e = (tid + (jj << 7)) << 2;
                int k = e >> 5, c = e & 31;
                cp16(Bs + nb * BS1T + k * 32 + c,
                     BT + (size_t)(k0 + k) * ldb + u0 + c);
            }
            CP_COMMIT();
            float* d = As + nb * AS_T;
            d[(ak + 0) * 32 + am] = av0.x; d[(ak + 1) * 32 + am] = av0.y;
            d[(ak + 2) * 32 + am] = av0.z; d[(ak + 3) * 32 + am] = av0.w;
            d[(ak + 4) * 32 + am] = av1.x; d[(ak + 5) * 32 + am] = av1.y;
            d[(ak + 6) * 32 + am] = av1.z; d[(ak + 7) * 32 + am] = av1.w;
            if (t + 2 < NT) {
                const float* p = Arow + ((t + 2) << 5);
                av0 = *(const float4*)(p);
                av1 = *(const float4*)(p + 4);
            }
        }
        const float* Ab = As + cb * AS_T;
        const float* Bb = Bs + cb * BS1T;
        #pragma unroll
        for (int k = 0; k < 32; k++) {
            double2 aL = *(const double2*)(Ab + k * 32 + (w << 3));
            double2 aH = *(const double2*)(Ab + k * 32 + (w << 3) + 4);
            unsigned long long bb = pack2s(Bb[k * 32 + lane]);
            ffma2(acc[0], __double_as_longlong(aL.x), bb);
            ffma2(acc[1], __double_as_longlong(aL.y), bb);
            ffma2(acc[2], __double_as_longlong(aH.x), bb);
            ffma2(acc[3], __double_as_longlong(aH.y), bb);
        }
        CP_WAIT0();
        __syncthreads();
    }
}

// ---------------- VW = emb @ Wx^T + b_ih  (whole vocab, once) ----------------
// grid (16, 1000), block 128
__global__ __launch_bounds__(128) void vw_gemm_kernel(
    const float* __restrict__ emb, const float* __restrict__ bihw)
{
    __shared__ __align__(16) float As[2 * AS_T];
    __shared__ __align__(16) float Bs[2 * BS3T];
    unsigned long long acc[3][4] = {};
    int u0 = blockIdx.x * 32, m0 = blockIdx.y * 32;
    gemm3v3(emb, E_, d_WxT, E_, m0, u0, acc, As, Bs);
    int lane = threadIdx.x & 31, w = threadIdx.x >> 5;
    int u = u0 + lane;
    float gr[8], gz[8], gn[8];
    unpack8(acc[0], gr); unpack8(acc[1], gz); unpack8(acc[2], gn);
    float br = bihw[u], bz = bihw[H_ + u], bn = bihw[2 * H_ + u];
    #pragma unroll
    for (int j = 0; j < 8; j++) {
        size_t m = m0 + (w << 3) + j;
        d_VW[m * G3_ + u]          = gr[j] + br;
        d_VW[m * G3_ + H_ + u]     = gz[j] + bz;
        d_VW[m * G3_ + 2 * H_ + u] = gn[j] + bn;
    }
}

// ---------------- worker GRU step ----------------
// grid (16, 8), block 128; frozen-block early exit
__global__ __launch_bounds__(128) void worker_step_kernel(
    const int* __restrict__ ids, const float* __restrict__ bhh, int t)
{
    int u0 = blockIdx.x * 32, m0 = blockIdx.y * 32;
    if (d_lens_s[m0] <= t - 2) return;
    __shared__ __align__(16) float As[2 * AS_T];
    __shared__ __align__(16) float Bs[2 * BS3T];
    const float* __restrict__ hwin = d_hw[t & 1];
    float* __restrict__ hwout      = d_hw[(t + 1) & 1];
    unsigned long long acc[3][4] = {};
    gemm3v3(hwin, H_, d_WhhT, H_, m0, u0, acc, As, Bs);

    int lane = threadIdx.x & 31, w = threadIdx.x >> 5;
    int u = u0 + lane;
    float gr[8], gz[8], gn[8];
    unpack8(acc[0], gr); unpack8(acc[1], gz); unpack8(acc[2], gn);
    float bhr = bhh[u], bhz = bhh[H_ + u], bhn = bhh[2 * H_ + u];
    #pragma unroll
    for (int j = 0; j < 8; j++) {
        int m   = m0 + (w << 3) + j;
        int len = d_lens_s[m];
        int id  = ids[d_perm[m] * S_ + t];
        const float* vw  = d_VW  + (size_t)id * G3_;
        const float* hpp = d_HPP + (size_t)m  * G3_;
        float r = sigf(vw[u] + hpp[u] + gr[j] + bhr);
        float z = sigf(vw[H_ + u] + hpp[H_ + u] + gz[j] + bhz);
        float n = tanh_fast(vw[2 * H_ + u] + hpp[2 * H_ + u] + r * (gn[j] + bhn));
        float hold = hwin[m * H_ + u];
        hwout[m * H_ + u] = (t < len) ? ((1.0f - z) * n + z * hold) : hold;
    }
}

// ---------------- planner: pi = hw @ pin^T + pin_b ----------------
// grid (16, 8), block 128
__global__ __launch_bounds__(128) void pi_kernel(const float* __restrict__ pinb, int t)
{
    int u0 = blockIdx.x * 32, m0 = blockIdx.y * 32;
    if (d_lens_s[m0] <= t - 8) return;
    __shared__ __align__(16) float As[2 * AS_T];
    __shared__ __align__(16) float Bs[2 * BS1T];
    const float* __restrict__ hw = d_hw[(t + 1) & 1];
    unsigned long long acc[4] = {};
    gemm1v3(hw, H_, d_pinT, H_, H_, m0, u0, acc, As, Bs);
    int lane = threadIdx.x & 31, w = threadIdx.x >> 5;
    int u = u0 + lane;
    float a[8]; unpack8(acc, a);
    float bb = pinb[u];
    #pragma unroll
    for (int j = 0; j < 8; j++) {
        int m = m0 + (w << 3) + j;
        d_pi[m * H_ + u] = a[j] + bb;
    }
}

// ---------------- planner GRU gates + update ----------------
// grid (16, 8), block 128
__global__ __launch_bounds__(128) void planner_step_kernel(
    const float* __restrict__ bip, const float* __restrict__ bhp, int t, int p)
{
    int u0 = blockIdx.x * 32, m0 = blockIdx.y * 32;
    if (d_lens_s[m0] <= t - 8) return;
    __shared__ __align__(16) float As[2 * AS_T];
    __shared__ __align__(16) float Bs[2 * BS3T];
    const float* __restrict__ hpin = d_hp[p & 1];
    float* __restrict__ hpout      = d_hp[(p + 1) & 1];
    unsigned long long acci[3][4] = {};
    unsigned long long acch[3][4] = {};
    gemm3v3(d_pi, H_, d_WipT, H_, m0, u0, acci, As, Bs);
    gemm3v3(hpin, H_, d_WhpT, H_, m0, u0, acch, As, Bs);

    int lane = threadIdx.x & 31, w = threadIdx.x >> 5;
    int u = u0 + lane;
    float ir[8], iz[8], in_[8], hr[8], hz[8], hn[8];
    unpack8(acci[0], ir); unpack8(acci[1], iz); unpack8(acci[2], in_);
    unpack8(acch[0], hr); unpack8(acch[1], hz); unpack8(acch[2], hn);
    float bir = bip[u], biz = bip[H_ + u], bin = bip[2 * H_ + u];
    float bhr = bhp[u], bhz = bhp[H_ + u], bhn = bhp[2 * H_ + u];
    #pragma unroll
    for (int j = 0; j < 8; j++) {
        int m   = m0 + (w << 3) + j;
        int len = d_lens_s[m];
        float r = sigf(ir[j] + bir + hr[j] + bhr);
        float z = sigf(iz[j] + biz + hz[j] + bhz);
        float n = tanh_fast(in_[j] + bin + r * (hn[j] + bhn));
        float hold = hpin[m * H_ + u];
        hpout[m * H_ + u] = (t < len) ? ((1.0f - z) * n + z * hold) : hold;
    }
}

// ---------------- HPP = hp @ WhT  (refresh after planner update) ----------------
// grid (16, 8), block 128
__global__ __launch_bounds__(128) void hpp_kernel(int t, int p)
{
    int u0 = blockIdx.x * 32, m0 = blockIdx.y * 32;
    if (d_lens_s[m0] <= t - 8) return;
    __shared__ __align__(16) float As[2 * AS_T];
    __shared__ __align__(16) float Bs[2 * BS3T];
    const float* __restrict__ hp = d_hp[(p + 1) & 1];
    unsigned long long acc[3][4] = {};
    gemm3v3(hp, H_, d_WhT, H_, m0, u0, acc, As, Bs);
    int lane = threadIdx.x & 31, w = threadIdx.x >> 5;
    int u = u0 + lane;
    float gr[8], gz[8], gn[8];
    unpack8(acc[0], gr); unpack8(acc[1], gz); unpack8(acc[2], gn);
    #pragma unroll
    for (int j = 0; j < 8; j++) {
        size_t m = m0 + (w << 3) + j;
        d_HPP[m * G3_ + u]          = gr[j];
        d_HPP[m * G3_ + H_ + u]     = gz[j];
        d_HPP[m * G3_ + 2 * H_ + u] = gn[j];
    }
}

// ---------------- fused = tanh([hw,hp] @ fus^T + fus_b) ----------------
__global__ __launch_bounds__(128) void fusion_kernel(const float* __restrict__ fusb)
{
    __shared__ __align__(16) float As[2 * AS_T];
    __shared__ __align__(16) float Bs[2 * BS1T];
    int u0 = blockIdx.x * 32, m0 = blockIdx.y * 32;
    unsigned long long acc[4] = {};
    gemm1v3(d_hw[0], H_, d_fusT, H_, H_, m0, u0, acc, As, Bs);
    gemm1v3(d_hp[0], H_, d_fusT + (size_t)H_ * H_, H_, H_, m0, u0, acc, As, Bs);
    int lane = threadIdx.x & 31, w = threadIdx.x >> 5;
    int u = u0 + lane;
    float a[8]; unpack8(acc, a);
    float bb = fusb[u];
    #pragma unroll
    for (int j = 0; j < 8; j++) {
        int m = m0 + (w << 3) + j;
        d_fused[m * H_ + u] = tanh_fast(a[j] + bb);
    }
}

// ---------------- h = relu(fused @ h1^T + h1_b) ----------------
__global__ __launch_bounds__(128) void h1_kernel(const float* __restrict__ h1b)
{
    __shared__ __align__(16) float As[2 * AS_T];
    __shared__ __align__(16) float Bs[2 * BS1T];
    int u0 = blockIdx.x * 32, m0 = blockIdx.y * 32;
    unsigned long long acc[4] = {};
    gemm1v3(d_fused, H_, d_h1T, H_, H_, m0, u0, acc, As, Bs);
    int lane = threadIdx.x & 31, w = threadIdx.x >> 5;
    int u = u0 + lane;
    float a[8]; unpack8(acc, a);
    float bb = h1b[u];
    #pragma unroll
    for (int j = 0; j < 8; j++) {
        int m = m0 + (w << 3) + j;
        d_relu[m * H_ + u] = fmaxf(a[j] + bb, 0.0f);
    }
}

// ---------------- out = h @ h2^T + h2_b (un-permutes rows) ----------------
__global__ void out_kernel(const float* __restrict__ h2w, const float* __restrict__ h2b,
                           float* __restrict__ out)
{
    int b = blockIdx.x;                 // permuted row
    int c = threadIdx.x >> 5;           // 0..9
    int lane = threadIdx.x & 31;
    float s = 0.0f;
    const float* hrow = d_relu + b * H_;
    const float* wrow = h2w + c * H_;
    for (int k = lane; k < H_; k += 32) s += hrow[k] * wrow[k];
    #pragma unroll
    for (int o = 16; o; o >>= 1) s += __shfl_down_sync(0xffffffff, s, o);
    if (lane == 0) out[d_perm[b] * 10 + c] = s + h2b[c];
}

// ---------------- host launcher (graph-capturable, no allocs) ----------------
extern "C" void kernel_launch(void* const* d_in, const int* in_sizes, int n_in,
                              void* d_out, int out_size)
{
    (void)in_sizes; (void)n_in; (void)out_size;
    const int*   ids  = (const int*)  d_in[0];
    const int*   lens = (const int*)  d_in[1];
    const float* emb  = (const float*)d_in[2];
    const float* wihw = (const float*)d_in[3];
    const float* whhw = (const float*)d_in[4];
    const float* bihw = (const float*)d_in[5];
    const float* bhhw = (const float*)d_in[6];
    const float* pinw = (const float*)d_in[7];
    const float* pinb = (const float*)d_in[8];
    const float* wihp = (const float*)d_in[9];
    const float* whhp = (const float*)d_in[10];
    const float* bihp = (const float*)d_in[11];
    const float* bhhp = (const float*)d_in[12];
    const float* fusw = (const float*)d_in[13];
    const float* fusb = (const float*)d_in[14];
    const float* h1w  = (const float*)d_in[15];
    const float* h1b  = (const float*)d_in[16];
    const float* h2w  = (const float*)d_in[17];
    const float* h2b  = (const float*)d_in[18];
    float* out = (float*)d_out;

    init_zero_kernel<<<(B_ * G3_ + 255) / 256, 256>>>();
    sort_kernel<<<1, B_>>>(lens);
    transpose_all_kernel<<<dim3(32, 48, 8), dim3(32, 32)>>>(
        wihw, whhw, wihp, whhp, pinw, fusw, h1w);
    vw_gemm_kernel<<<dim3(16, VOCAB_ / 32), 128>>>(emb, bihw);

    for (int t = 0; t < S_; t++) {
        worker_step_kernel<<<dim3(16, 8), 128>>>(ids, bhhw, t);
        if (((t + 1) & 3) == 0) {
            int p = ((t + 1) >> 2) - 1;          // 0..127
            pi_kernel<<<dim3(16, 8), 128>>>(pinb, t);
            planner_step_kernel<<<dim3(16, 8), 128>>>(bihp, bhhp, t, p);
            hpp_kernel<<<dim3(16, 8), 128>>>(t, p);
        }
    }

    fusion_kernel<<<dim3(16, 8), 128>>>(fusb);
    h1_kernel<<<dim3(16, 8), 128>>>(h1b);
    out_kernel<<<B_, 320>>>(h2w, h2b, out);
}

// round 16
// speedup vs baseline: 1.0800x; 1.0800x over previous
#include <cuda_runtime.h>
#include <math.h>

#define B_    256
#define S_    512
#define E_    256
#define H_    512
#define G3_   1536      // 3*H
#define VOCAB_ 32000

// ---------------- device scratch (no allocation allowed) ----------------
__device__ float d_VW[(size_t)VOCAB_ * G3_]; // emb @ Wx^T + b_ih  (196.6 MB)
__device__ float d_WxT [E_ * G3_];           // [k][g*512+u]  (w_ih_w cols 0..255)
__device__ float d_WhT [H_ * G3_];           // w_ih_w cols 256..767 transposed
__device__ float d_WhhT[H_ * G3_];           // w_hh_w transposed
__device__ float d_WipT[H_ * G3_];           // w_ih_p transposed
__device__ float d_WhpT[H_ * G3_];           // w_hh_p transposed
__device__ float d_pinT[H_ * H_];            // pin_w transposed [k][c]
__device__ float d_fusT[2 * H_ * H_];        // fus_w transposed
__device__ float d_h1T [H_ * H_];            // h1_w transposed
__device__ float d_hw[2][B_ * H_];           // worker hidden (permuted), double buffered
__device__ float d_hp[2][B_ * H_];           // planner hidden (permuted), double buffered
__device__ float d_HPP[B_ * G3_];            // hp @ WhT (permuted)
__device__ float d_pi [B_ * H_];             // planner input projection (permuted)
__device__ float d_fused[B_ * H_];
__device__ float d_relu [B_ * H_];
__device__ int   d_perm[B_];                 // sorted-rank -> original batch index
__device__ int   d_lens_s[B_];               // lengths sorted descending

// ---------------- math helpers ----------------
__device__ __forceinline__ float sigf(float x) {
    return 1.0f / (1.0f + __expf(-x));
}
__device__ __forceinline__ float tanh_fast(float x) {
    float ax = fabsf(x);
    float e  = __expf(-2.0f * ax);
    float t  = (1.0f - e) / (1.0f + e);
    return copysignf(t, x);
}
__device__ __forceinline__ unsigned long long pack2s(float v) {
    unsigned long long r;
    asm("mov.b64 %0, {%1, %1};" : "=l"(r) : "f"(v));
    return r;
}
__device__ __forceinline__ float2 unpack2(unsigned long long v) {
    float2 f;
    asm("mov.b64 {%0, %1}, %2;" : "=f"(f.x), "=f"(f.y) : "l"(v));
    return f;
}
__device__ __forceinline__ void ffma2(unsigned long long &d,
                                      unsigned long long a, unsigned long long b) {
    asm("fma.rn.f32x2 %0, %1, %2, %0;" : "+l"(d) : "l"(a), "l"(b));
}
__device__ __forceinline__ void cp16(float* smem_dst, const float* gmem_src) {
    unsigned s = (unsigned)__cvta_generic_to_shared(smem_dst);
    asm volatile("cp.async.cg.shared.global [%0], [%1], 16;\n" :: "r"(s), "l"(gmem_src));
}
#define CP_COMMIT() asm volatile("cp.async.commit_group;\n" ::)
#define CP_WAIT0()  asm volatile("cp.async.wait_group 0;\n" ::)

// ---------------- init ----------------
__global__ void init_zero_kernel() {
    int i = blockIdx.x * blockDim.x + threadIdx.x;
    if (i < B_ * H_) { d_hw[0][i] = 0.0f; d_hp[0][i] = 0.0f; }
    if (i < B_ * G3_) d_HPP[i] = 0.0f;
}

// ---------------- sort batch rows by descending length (deterministic) ----------------
__global__ void sort_kernel(const int* __restrict__ lens) {
    __shared__ int L[B_];
    int i = threadIdx.x;
    L[i] = lens[i];
    __syncthreads();
    int li = L[i];
    int rank = 0;
    for (int j = 0; j < B_; j++) {
        int lj = L[j];
        if (lj > li || (lj == li && j < i)) rank++;
    }
    d_perm[rank]   = i;
    d_lens_s[rank] = li;
}

// ---------------- transpose all weight matrices ----------------
__global__ void transpose_all_kernel(
    const float* __restrict__ wihw, const float* __restrict__ whhw,
    const float* __restrict__ wihp, const float* __restrict__ whhp,
    const float* __restrict__ pinw, const float* __restrict__ fusw,
    const float* __restrict__ h1w)
{
    const float* src; float* dst; int R, K, ld, coff;
    switch (blockIdx.z) {
        case 0: src=wihw; dst=d_WxT;  R=G3_; K=E_;    ld=E_+H_; coff=0;   break;
        case 1: src=wihw; dst=d_WhT;  R=G3_; K=H_;    ld=E_+H_; coff=E_;  break;
        case 2: src=whhw; dst=d_WhhT; R=G3_; K=H_;    ld=H_;    coff=0;   break;
        case 3: src=wihp; dst=d_WipT; R=G3_; K=H_;    ld=H_;    coff=0;   break;
        case 4: src=whhp; dst=d_WhpT; R=G3_; K=H_;    ld=H_;    coff=0;   break;
        case 5: src=pinw; dst=d_pinT; R=H_;  K=H_;    ld=H_;    coff=0;   break;
        case 6: src=fusw; dst=d_fusT; R=H_;  K=2*H_;  ld=2*H_;  coff=0;   break;
        default:src=h1w;  dst=d_h1T;  R=H_;  K=H_;    ld=H_;    coff=0;   break;
    }
    __shared__ float tile[32][33];
    int r0 = blockIdx.y * 32, k0 = blockIdx.x * 32;
    int r = r0 + threadIdx.y, k = k0 + threadIdx.x;
    if (r < R && k < K) tile[threadIdx.y][threadIdx.x] = src[r * ld + coff + k];
    __syncthreads();
    int rr = r0 + threadIdx.x, kk = k0 + threadIdx.y;
    if (rr < R && kk < K) dst[(size_t)kk * R + rr] = tile[threadIdx.x][threadIdx.y];
}

// ============== GEMM v4: split-K, 256 threads (2 halves x 4 warps x 8 rows) ==============
// Tile: 32 rows x 32 units (x3 gates). Warps 0-3 process k in [0,K/2),
// warps 4-7 process [K/2,K). Each warp: lane = unit, 8 rows.
// Per warp per k: 2 broadcast LDS.128 (A, 4 f32x2 row-pairs) + 3 full LDS.32 (B)
// + 12 FFMA2. Half-sums merged via smem reduction; epilogue on half 0.
#define ASZ  1024   // floats per A buffer (32k x 32m)
#define BSZ3 3072   // floats per B buffer (32k x 96)
#define BSZ1 1024   // floats per B buffer (32k x 32)
#define SMEM3_BYTES ((4 * ASZ + 4 * BSZ3) * 4)   // 65,536
#define SMEM1_BYTES ((4 * ASZ + 4 * BSZ1) * 4)   // 32,768

__device__ __forceinline__ void gemm3v4(
    const float* __restrict__ A, int lda,
    const float* __restrict__ BT, int K,
    int m0, int u0,
    unsigned long long acc[3][4],
    float* __restrict__ As, float* __restrict__ Bs)
{
    const int tid  = threadIdx.x;
    const int half = tid >> 7;
    const int hid  = tid & 127;
    const int lane = hid & 31;
    const int w4   = hid >> 5;           // warp-in-half 0..3
    const int kbase = half * (K >> 1);
    const int NT   = K >> 6;             // tiles per half
    const int am   = lane;
    const int ak   = w4 << 3;
    float* Ash = As + half * 2 * ASZ;
    float* Bsh = Bs + half * 2 * BSZ3;
    const float* Arow = A + (size_t)(m0 + am) * lda + kbase + ak;

    float4 av0 = *(const float4*)(Arow);
    float4 av1 = *(const float4*)(Arow + 4);
    #pragma unroll
    for (int jj = 0; jj < 6; jj++) {
        int e = (hid + (jj << 7)) << 2;
        int k = e / 96, c = e % 96;
        cp16(Bsh + k * 96 + c,
             BT + (size_t)(kbase + k) * G3_ + (c >> 5) * H_ + u0 + (c & 31));
    }
    CP_COMMIT();
    Ash[(ak + 0) * 32 + am] = av0.x; Ash[(ak + 1) * 32 + am] = av0.y;
    Ash[(ak + 2) * 32 + am] = av0.z; Ash[(ak + 3) * 32 + am] = av0.w;
    Ash[(ak + 4) * 32 + am] = av1.x; Ash[(ak + 5) * 32 + am] = av1.y;
    Ash[(ak + 6) * 32 + am] = av1.z; Ash[(ak + 7) * 32 + am] = av1.w;
    if (NT > 1) {
        av0 = *(const float4*)(Arow + 32);
        av1 = *(const float4*)(Arow + 36);
    }
    CP_WAIT0();
    __syncthreads();

    for (int t = 0; t < NT; t++) {
        const int cb = t & 1, nb = (t + 1) & 1;
        if (t + 1 < NT) {
            int k0 = (t + 1) << 5;
            #pragma unroll
            for (int jj = 0; jj < 6; jj++) {
                int e = (hid + (jj << 7)) << 2;
                int k = e / 96, c = e % 96;
                cp16(Bsh + nb * BSZ3 + k * 96 + c,
                     BT + (size_t)(kbase + k0 + k) * G3_ + (c >> 5) * H_ + u0 + (c & 31));
            }
            CP_COMMIT();
            float* d = Ash + nb * ASZ;
            d[(ak + 0) * 32 + am] = av0.x; d[(ak + 1) * 32 + am] = av0.y;
            d[(ak + 2) * 32 + am] = av0.z; d[(ak + 3) * 32 + am] = av0.w;
            d[(ak + 4) * 32 + am] = av1.x; d[(ak + 5) * 32 + am] = av1.y;
            d[(ak + 6) * 32 + am] = av1.z; d[(ak + 7) * 32 + am] = av1.w;
            if (t + 2 < NT) {
                const float* p = Arow + ((t + 2) << 5);
                av0 = *(const float4*)(p);
                av1 = *(const float4*)(p + 4);
            }
        }
        const float* Ab = Ash + cb * ASZ;
        const float* Bb = Bsh + cb * BSZ3;
        #pragma unroll
        for (int k = 0; k < 32; k++) {
            double2 aL = *(const double2*)(Ab + k * 32 + (w4 << 3));
            double2 aH = *(const double2*)(Ab + k * 32 + (w4 << 3) + 4);
            unsigned long long a0 = __double_as_longlong(aL.x);
            unsigned long long a1 = __double_as_longlong(aL.y);
            unsigned long long a2 = __double_as_longlong(aH.x);
            unsigned long long a3 = __double_as_longlong(aH.y);
            unsigned long long br = pack2s(Bb[k * 96 + lane]);
            unsigned long long bz = pack2s(Bb[k * 96 + 32 + lane]);
            unsigned long long bn = pack2s(Bb[k * 96 + 64 + lane]);
            ffma2(acc[0][0], a0, br); ffma2(acc[0][1], a1, br);
            ffma2(acc[0][2], a2, br); ffma2(acc[0][3], a3, br);
            ffma2(acc[1][0], a0, bz); ffma2(acc[1][1], a1, bz);
            ffma2(acc[1][2], a2, bz); ffma2(acc[1][3], a3, bz);
            ffma2(acc[2][0], a0, bn); ffma2(acc[2][1], a1, bn);
            ffma2(acc[2][2], a2, bn); ffma2(acc[2][3], a3, bn);
        }
        CP_WAIT0();
        __syncthreads();
    }
}

__device__ __forceinline__ void gemm1v4(
    const float* __restrict__ A, int lda,
    const float* __restrict__ BT, int ldb, int K,
    int m0, int u0,
    unsigned long long acc[4],
    float* __restrict__ As, float* __restrict__ Bs)
{
    const int tid  = threadIdx.x;
    const int half = tid >> 7;
    const int hid  = tid & 127;
    const int lane = hid & 31;
    const int w4   = hid >> 5;
    const int kbase = half * (K >> 1);
    const int NT   = K >> 6;
    const int am   = lane;
    const int ak   = w4 << 3;
    float* Ash = As + half * 2 * ASZ;
    float* Bsh = Bs + half * 2 * BSZ1;
    const float* Arow = A + (size_t)(m0 + am) * lda + kbase + ak;

    float4 av0 = *(const float4*)(Arow);
    float4 av1 = *(const float4*)(Arow + 4);
    #pragma unroll
    for (int jj = 0; jj < 2; jj++) {
        int e = (hid + (jj << 7)) << 2;
        int k = e >> 5, c = e & 31;
        cp16(Bsh + k * 32 + c, BT + (size_t)(kbase + k) * ldb + u0 + c);
    }
    CP_COMMIT();
    Ash[(ak + 0) * 32 + am] = av0.x; Ash[(ak + 1) * 32 + am] = av0.y;
    Ash[(ak + 2) * 32 + am] = av0.z; Ash[(ak + 3) * 32 + am] = av0.w;
    Ash[(ak + 4) * 32 + am] = av1.x; Ash[(ak + 5) * 32 + am] = av1.y;
    Ash[(ak + 6) * 32 + am] = av1.z; Ash[(ak + 7) * 32 + am] = av1.w;
    if (NT > 1) {
        av0 = *(const float4*)(Arow + 32);
        av1 = *(const float4*)(Arow + 36);
    }
    CP_WAIT0();
    __syncthreads();

    for (int t = 0; t < NT; t++) {
        const int cb = t & 1, nb = (t + 1) & 1;
        if (t + 1 < NT) {
            int k0 = (t + 1) << 5;
            #pragma unroll
            for (int jj = 0; jj < 2; jj++) {
                int e = (hid + (jj << 7)) << 2;
                int k = e >> 5, c = e & 31;
                cp16(Bsh + nb * BSZ1 + k * 32 + c,
                     BT + (size_t)(kbase + k0 + k) * ldb + u0 + c);
            }
            CP_COMMIT();
            float* d = Ash + nb * ASZ;
            d[(ak + 0) * 32 + am] = av0.x; d[(ak + 1) * 32 + am] = av0.y;
            d[(ak + 2) * 32 + am] = av0.z; d[(ak + 3) * 32 + am] = av0.w;
            d[(ak + 4) * 32 + am] = av1.x; d[(ak + 5) * 32 + am] = av1.y;
            d[(ak + 6) * 32 + am] = av1.z; d[(ak + 7) * 32 + am] = av1.w;
            if (t + 2 < NT) {
                const float* p = Arow + ((t + 2) << 5);
                av0 = *(const float4*)(p);
                av1 = *(const float4*)(p + 4);
            }
        }
        const float* Ab = Ash + cb * ASZ;
        const float* Bb = Bsh + cb * BSZ1;
        #pragma unroll
        for (int k = 0; k < 32; k++) {
            double2 aL = *(const double2*)(Ab + k * 32 + (w4 << 3));
            double2 aH = *(const double2*)(Ab + k * 32 + (w4 << 3) + 4);
            unsigned long long bb = pack2s(Bb[k * 32 + lane]);
            ffma2(acc[0], __double_as_longlong(aL.x), bb);
            ffma2(acc[1], __double_as_longlong(aL.y), bb);
            ffma2(acc[2], __double_as_longlong(aH.x), bb);
            ffma2(acc[3], __double_as_longlong(aH.y), bb);
        }
        CP_WAIT0();
        __syncthreads();
    }
}

// merge half-1 accumulators into half-0; outputs floats for half-0 threads
__device__ __forceinline__ void reduce3(const unsigned long long acc[3][4],
                                        float o[3][8], float* scratch)
{
    const int tid  = threadIdx.x;
    const int half = tid >> 7;
    const int hid  = tid & 127;
    unsigned long long* red = (unsigned long long*)scratch;
    if (half) {
        #pragma unroll
        for (int g = 0; g < 3; g++)
            #pragma unroll
            for (int p = 0; p < 4; p++)
                red[hid * 12 + g * 4 + p] = acc[g][p];
    }
    __syncthreads();
    if (!half) {
        #pragma unroll
        for (int g = 0; g < 3; g++)
            #pragma unroll
            for (int p = 0; p < 4; p++) {
                float2 a = unpack2(acc[g][p]);
                float2 b = unpack2(red[hid * 12 + g * 4 + p]);
                o[g][2 * p]     = a.x + b.x;
                o[g][2 * p + 1] = a.y + b.y;
            }
    }
    __syncthreads();
}

__device__ __forceinline__ void reduce1(const unsigned long long acc[4],
                                        float o[8], float* scratch)
{
    const int tid  = threadIdx.x;
    const int half = tid >> 7;
    const int hid  = tid & 127;
    unsigned long long* red = (unsigned long long*)scratch;
    if (half) {
        #pragma unroll
        for (int p = 0; p < 4; p++) red[hid * 4 + p] = acc[p];
    }
    __syncthreads();
    if (!half) {
        #pragma unroll
        for (int p = 0; p < 4; p++) {
            float2 a = unpack2(acc[p]);
            float2 b = unpack2(red[hid * 4 + p]);
            o[2 * p]     = a.x + b.x;
            o[2 * p + 1] = a.y + b.y;
        }
    }
    __syncthreads();
}

// ---------------- VW = emb @ Wx^T + b_ih  (whole vocab, once) ----------------
// grid (16, 1000), block 256
__global__ __launch_bounds__(256) void vw_gemm_kernel(
    const float* __restrict__ emb, const float* __restrict__ bihw)
{
    extern __shared__ __align__(16) float smem[];
    float* As = smem;
    float* Bs = smem + 4 * ASZ;
    unsigned long long acc[3][4] = {};
    int u0 = blockIdx.x * 32, m0 = blockIdx.y * 32;
    gemm3v4(emb, E_, d_WxT, E_, m0, u0, acc, As, Bs);
    float g[3][8];
    reduce3(acc, g, Bs);
    if (threadIdx.x >> 7) return;
    int hid = threadIdx.x & 127, lane = hid & 31, w4 = hid >> 5;
    int u = u0 + lane;
    float br = bihw[u], bz = bihw[H_ + u], bn = bihw[2 * H_ + u];
    #pragma unroll
    for (int j = 0; j < 8; j++) {
        size_t m = m0 + (w4 << 3) + j;
        d_VW[m * G3_ + u]          = g[0][j] + br;
        d_VW[m * G3_ + H_ + u]     = g[1][j] + bz;
        d_VW[m * G3_ + 2 * H_ + u] = g[2][j] + bn;
    }
}

// ---------------- worker GRU step ----------------
// grid (16, 8), block 256; frozen-block early exit
__global__ __launch_bounds__(256) void worker_step_kernel(
    const int* __restrict__ ids, const float* __restrict__ bhh, int t)
{
    int u0 = blockIdx.x * 32, m0 = blockIdx.y * 32;
    if (d_lens_s[m0] <= t - 2) return;
    extern __shared__ __align__(16) float smem[];
    float* As = smem;
    float* Bs = smem + 4 * ASZ;
    const float* __restrict__ hwin = d_hw[t & 1];
    float* __restrict__ hwout      = d_hw[(t + 1) & 1];
    unsigned long long acc[3][4] = {};
    gemm3v4(hwin, H_, d_WhhT, H_, m0, u0, acc, As, Bs);
    float g[3][8];
    reduce3(acc, g, Bs);
    if (threadIdx.x >> 7) return;
    int hid = threadIdx.x & 127, lane = hid & 31, w4 = hid >> 5;
    int u = u0 + lane;
    float bhr = bhh[u], bhz = bhh[H_ + u], bhn = bhh[2 * H_ + u];
    #pragma unroll
    for (int j = 0; j < 8; j++) {
        int m   = m0 + (w4 << 3) + j;
        int len = d_lens_s[m];
        int id  = ids[d_perm[m] * S_ + t];
        const float* vw  = d_VW  + (size_t)id * G3_;
        const float* hpp = d_HPP + (size_t)m  * G3_;
        float r = sigf(vw[u] + hpp[u] + g[0][j] + bhr);
        float z = sigf(vw[H_ + u] + hpp[H_ + u] + g[1][j] + bhz);
        float n = tanh_fast(vw[2 * H_ + u] + hpp[2 * H_ + u] + r * (g[2][j] + bhn));
        float hold = hwin[m * H_ + u];
        hwout[m * H_ + u] = (t < len) ? ((1.0f - z) * n + z * hold) : hold;
    }
}

// ---------------- planner: pi = hw @ pin^T + pin_b ----------------
// grid (16, 8), block 256
__global__ __launch_bounds__(256) void pi_kernel(const float* __restrict__ pinb, int t)
{
    int u0 = blockIdx.x * 32, m0 = blockIdx.y * 32;
    if (d_lens_s[m0] <= t - 8) return;
    extern __shared__ __align__(16) float smem[];
    float* As = smem;
    float* Bs = smem + 4 * ASZ;
    const float* __restrict__ hw = d_hw[(t + 1) & 1];
    unsigned long long acc[4] = {};
    gemm1v4(hw, H_, d_pinT, H_, H_, m0, u0, acc, As, Bs);
    float a[8];
    reduce1(acc, a, Bs);
    if (threadIdx.x >> 7) return;
    int hid = threadIdx.x & 127, lane = hid & 31, w4 = hid >> 5;
    int u = u0 + lane;
    float bb = pinb[u];
    #pragma unroll
    for (int j = 0; j < 8; j++) {
        int m = m0 + (w4 << 3) + j;
        d_pi[m * H_ + u] = a[j] + bb;
    }
}

// ---------------- planner GRU gates + update ----------------
// grid (16, 8), block 256
__global__ __launch_bounds__(256) void planner_step_kernel(
    const float* __restrict__ bip, const float* __restrict__ bhp, int t, int p)
{
    int u0 = blockIdx.x * 32, m0 = blockIdx.y * 32;
    if (d_lens_s[m0] <= t - 8) return;
    extern __shared__ __align__(16) float smem[];
    float* As = smem;
    float* Bs = smem + 4 * ASZ;
    const float* __restrict__ hpin = d_hp[p & 1];
    float* __restrict__ hpout      = d_hp[(p + 1) & 1];
    unsigned long long acci[3][4] = {};
    unsigned long long acch[3][4] = {};
    gemm3v4(d_pi, H_, d_WipT, H_, m0, u0, acci, As, Bs);
    gemm3v4(hpin, H_, d_WhpT, H_, m0, u0, acch, As, Bs);
    float gi[3][8], gh[3][8];
    reduce3(acci, gi, Bs);
    reduce3(acch, gh, Bs);
    if (threadIdx.x >> 7) return;
    int hid = threadIdx.x & 127, lane = hid & 31, w4 = hid >> 5;
    int u = u0 + lane;
    float bir = bip[u], biz = bip[H_ + u], bin = bip[2 * H_ + u];
    float bhr = bhp[u], bhz = bhp[H_ + u], bhn = bhp[2 * H_ + u];
    #pragma unroll
    for (int j = 0; j < 8; j++) {
        int m   = m0 + (w4 << 3) + j;
        int len = d_lens_s[m];
        float r = sigf(gi[0][j] + bir + gh[0][j] + bhr);
        float z = sigf(gi[1][j] + biz + gh[1][j] + bhz);
        float n = tanh_fast(gi[2][j] + bin + r * (gh[2][j] + bhn));
        float hold = hpin[m * H_ + u];
        hpout[m * H_ + u] = (t < len) ? ((1.0f - z) * n + z * hold) : hold;
    }
}

// ---------------- HPP = hp @ WhT  (refresh after planner update) ----------------
// grid (16, 8), block 256
__global__ __launch_bounds__(256) void hpp_kernel(int t, int p)
{
    int u0 = blockIdx.x * 32, m0 = blockIdx.y * 32;
    if (d_lens_s[m0] <= t - 8) return;
    extern __shared__ __align__(16) float smem[];
    float* As = smem;
    float* Bs = smem + 4 * ASZ;
    const float* __restrict__ hp = d_hp[(p + 1) & 1];
    unsigned long long acc[3][4] = {};
    gemm3v4(hp, H_, d_WhT, H_, m0, u0, acc, As, Bs);
    float g[3][8];
    reduce3(acc, g, Bs);
    if (threadIdx.x >> 7) return;
    int hid = threadIdx.x & 127, lane = hid & 31, w4 = hid >> 5;
    int u = u0 + lane;
    #pragma unroll
    for (int j = 0; j < 8; j++) {
        size_t m = m0 + (w4 << 3) + j;
        d_HPP[m * G3_ + u]          = g[0][j];
        d_HPP[m * G3_ + H_ + u]     = g[1][j];
        d_HPP[m * G3_ + 2 * H_ + u] = g[2][j];
    }
}

// ---------------- fused = tanh([hw,hp] @ fus^T + fus_b) ----------------
__global__ __launch_bounds__(256) void fusion_kernel(const float* __restrict__ fusb)
{
    extern __shared__ __align__(16) float smem[];
    float* As = smem;
    float* Bs = smem + 4 * ASZ;
    int u0 = blockIdx.x * 32, m0 = blockIdx.y * 32;
    unsigned long long acc[4] = {};
    gemm1v4(d_hw[0], H_, d_fusT, H_, H_, m0, u0, acc, As, Bs);
    gemm1v4(d_hp[0], H_, d_fusT + (size_t)H_ * H_, H_, H_, m0, u0, acc, As, Bs);
    float a[8];
    reduce1(acc, a, Bs);
    if (threadIdx.x >> 7) return;
    int hid = threadIdx.x & 127, lane = hid & 31, w4 = hid >> 5;
    int u = u0 + lane;
    float bb = fusb[u];
    #pragma unroll
    for (int j = 0; j < 8; j++) {
        int m = m0 + (w4 << 3) + j;
        d_fused[m * H_ + u] = tanh_fast(a[j] + bb);
    }
}

// ---------------- h = relu(fused @ h1^T + h1_b) ----------------
__global__ __launch_bounds__(256) void h1_kernel(const float* __restrict__ h1b)
{
    extern __shared__ __align__(16) float smem[];
    float* As = smem;
    float* Bs = smem + 4 * ASZ;
    int u0 = blockIdx.x * 32, m0 = blockIdx.y * 32;
    unsigned long long acc[4] = {};
    gemm1v4(d_fused, H_, d_h1T, H_, H_, m0, u0, acc, As, Bs);
    float a[8];
    reduce1(acc, a, Bs);
    if (threadIdx.x >> 7) return;
    int hid = threadIdx.x & 127, lane = hid & 31, w4 = hid >> 5;
    int u = u0 + lane;
    float bb = h1b[u];
    #pragma unroll
    for (int j = 0; j < 8; j++) {
        int m = m0 + (w4 << 3) + j;
        d_relu[m * H_ + u] = fmaxf(a[j] + bb, 0.0f);
    }
}

// ---------------- out = h @ h2^T + h2_b (un-permutes rows) ----------------
__global__ void out_kernel(const float* __restrict__ h2w, const float* __restrict__ h2b,
                           float* __restrict__ out)
{
    int b = blockIdx.x;                 // permuted row
    int c = threadIdx.x >> 5;           // 0..9
    int lane = threadIdx.x & 31;
    float s = 0.0f;
    const float* hrow = d_relu + b * H_;
    const float* wrow = h2w + c * H_;
    for (int k = lane; k < H_; k += 32) s += hrow[k] * wrow[k];
    #pragma unroll
    for (int o = 16; o; o >>= 1) s += __shfl_down_sync(0xffffffff, s, o);
    if (lane == 0) out[d_perm[b] * 10 + c] = s + h2b[c];
}

// ---------------- host launcher (graph-capturable, no allocs) ----------------
extern "C" void kernel_launch(void* const* d_in, const int* in_sizes, int n_in,
                              void* d_out, int out_size)
{
    (void)in_sizes; (void)n_in; (void)out_size;
    const int*   ids  = (const int*)  d_in[0];
    const int*   lens = (const int*)  d_in[1];
    const float* emb  = (const float*)d_in[2];
    const float* wihw = (const float*)d_in[3];
    const float* whhw = (const float*)d_in[4];
    const float* bihw = (const float*)d_in[5];
    const float* bhhw = (const float*)d_in[6];
    const float* pinw = (const float*)d_in[7];
    const float* pinb = (const float*)d_in[8];
    const float* wihp = (const float*)d_in[9];
    const float* whhp = (const float*)d_in[10];
    const float* bihp = (const float*)d_in[11];
    const float* bhhp = (const float*)d_in[12];
    const float* fusw = (const float*)d_in[13];
    const float* fusb = (const float*)d_in[14];
    const float* h1w  = (const float*)d_in[15];
    const float* h1b  = (const float*)d_in[16];
    const float* h2w  = (const float*)d_in[17];
    const float* h2b  = (const float*)d_in[18];
    float* out = (float*)d_out;

    // dynamic-smem opt-in (idempotent; not an allocation)
    static int attr_done = 0;
    if (!attr_done) {
        cudaFuncSetAttribute(vw_gemm_kernel,      cudaFuncAttributeMaxDynamicSharedMemorySize, SMEM3_BYTES);
        cudaFuncSetAttribute(worker_step_kernel,  cudaFuncAttributeMaxDynamicSharedMemorySize, SMEM3_BYTES);
        cudaFuncSetAttribute(planner_step_kernel, cudaFuncAttributeMaxDynamicSharedMemorySize, SMEM3_BYTES);
        cudaFuncSetAttribute(hpp_kernel,          cudaFuncAttributeMaxDynamicSharedMemorySize, SMEM3_BYTES);
        cudaFuncSetAttribute(pi_kernel,           cudaFuncAttributeMaxDynamicSharedMemorySize, SMEM1_BYTES);
        cudaFuncSetAttribute(fusion_kernel,       cudaFuncAttributeMaxDynamicSharedMemorySize, SMEM1_BYTES);
        cudaFuncSetAttribute(h1_kernel,           cudaFuncAttributeMaxDynamicSharedMemorySize, SMEM1_BYTES);
        attr_done = 1;
    }

    init_zero_kernel<<<(B_ * G3_ + 255) / 256, 256>>>();
    sort_kernel<<<1, B_>>>(lens);
    transpose_all_kernel<<<dim3(32, 48, 8), dim3(32, 32)>>>(
        wihw, whhw, wihp, whhp, pinw, fusw, h1w);
    vw_gemm_kernel<<<dim3(16, VOCAB_ / 32), 256, SMEM3_BYTES>>>(emb, bihw);

    for (int t = 0; t < S_; t++) {
        worker_step_kernel<<<dim3(16, 8), 256, SMEM3_BYTES>>>(ids, bhhw, t);
        if (((t + 1) & 3) == 0) {
            int p = ((t + 1) >> 2) - 1;          // 0..127
            pi_kernel<<<dim3(16, 8), 256, SMEM1_BYTES>>>(pinb, t);
            planner_step_kernel<<<dim3(16, 8), 256, SMEM3_BYTES>>>(bihp, bhhp, t, p);
            hpp_kernel<<<dim3(16, 8), 256, SMEM3_BYTES>>>(t, p);
        }
    }

    fusion_kernel<<<dim3(16, 8), 256, SMEM1_BYTES>>>(fusb);
    h1_kernel<<<dim3(16, 8), 256, SMEM1_BYTES>>>(h1b);
    out_kernel<<<B_, 320>>>(h2w, h2b, out);
}

// round 17
// speedup vs baseline: 1.2167x; 1.1266x over previous
#include <cuda_runtime.h>
#include <math.h>

#define B_    256
#define S_    512
#define E_    256
#define H_    512
#define G3_   1536      // 3*H
#define VOCAB_ 32000
#define NBLK_ 128       // persistent grid size (16 x 8)

// ---------------- device scratch (no allocation allowed) ----------------
__device__ float d_VW[(size_t)VOCAB_ * G3_]; // emb @ Wx^T + b_ih  (196.6 MB)
__device__ float d_WxT [E_ * G3_];           // [k][g*512+u]  (w_ih_w cols 0..255)
__device__ float d_WhT [H_ * G3_];           // w_ih_w cols 256..767 transposed
__device__ float d_WhhT[H_ * G3_];           // w_hh_w transposed
__device__ float d_WipT[H_ * G3_];           // w_ih_p transposed
__device__ float d_WhpT[H_ * G3_];           // w_hh_p transposed
__device__ float d_pinT[H_ * H_];            // pin_w transposed [k][c]
__device__ float d_fusT[2 * H_ * H_];        // fus_w transposed
__device__ float d_h1T [H_ * H_];            // h1_w transposed
__device__ float d_hw[2][B_ * H_];           // worker hidden (permuted), double buffered
__device__ float d_hp[2][B_ * H_];           // planner hidden (permuted), double buffered
__device__ float d_HPP[B_ * G3_];            // hp @ WhT (permuted)
__device__ float d_pi [B_ * H_];             // planner input projection (permuted)
__device__ float d_fused[B_ * H_];
__device__ float d_relu [B_ * H_];
__device__ int   d_perm[B_];                 // sorted-rank -> original batch index
__device__ int   d_lens_s[B_];               // lengths sorted descending
__device__ unsigned d_gbar;                  // grid-barrier counter (reset by init)

// ---------------- math helpers ----------------
__device__ __forceinline__ float sigf(float x) {
    return 1.0f / (1.0f + __expf(-x));
}
__device__ __forceinline__ float tanh_fast(float x) {
    float ax = fabsf(x);
    float e  = __expf(-2.0f * ax);
    float t  = (1.0f - e) / (1.0f + e);
    return copysignf(t, x);
}
__device__ __forceinline__ unsigned long long pack2s(float v) {
    unsigned long long r;
    asm("mov.b64 %0, {%1, %1};" : "=l"(r) : "f"(v));
    return r;
}
__device__ __forceinline__ float2 unpack2(unsigned long long v) {
    float2 f;
    asm("mov.b64 {%0, %1}, %2;" : "=f"(f.x), "=f"(f.y) : "l"(v));
    return f;
}
__device__ __forceinline__ void ffma2(unsigned long long &d,
                                      unsigned long long a, unsigned long long b) {
    asm("fma.rn.f32x2 %0, %1, %2, %0;" : "+l"(d) : "l"(a), "l"(b));
}
__device__ __forceinline__ void cp16(float* smem_dst, const float* gmem_src) {
    unsigned s = (unsigned)__cvta_generic_to_shared(smem_dst);
    asm volatile("cp.async.cg.shared.global [%0], [%1], 16;\n" :: "r"(s), "l"(gmem_src));
}
#define CP_COMMIT() asm volatile("cp.async.commit_group;\n" ::)
#define CP_WAIT0()  asm volatile("cp.async.wait_group 0;\n" ::)

// grid barrier: all NBLK_ blocks co-resident (grid <= SM count, 1 CTA/SM).
// release: syncthreads -> threadfence -> atomic arrive. acquire: poll L2 via
// atomics, then threadfence (CCTL.IVALL -> L1 invalidate) -> syncthreads.
__device__ __forceinline__ void gbar(unsigned &tgt) {
    tgt += NBLK_;
    __syncthreads();
    if (threadIdx.x == 0) {
        __threadfence();
        atomicAdd(&d_gbar, 1u);
        while (atomicAdd(&d_gbar, 0u) < tgt) { }
        __threadfence();
    }
    __syncthreads();
}

// ---------------- init ----------------
__global__ void init_zero_kernel() {
    int i = blockIdx.x * blockDim.x + threadIdx.x;
    if (i == 0) d_gbar = 0;
    if (i < B_ * H_) { d_hw[0][i] = 0.0f; d_hp[0][i] = 0.0f; }
    if (i < B_ * G3_) d_HPP[i] = 0.0f;
}

// ---------------- sort batch rows by descending length (deterministic) ----------------
__global__ void sort_kernel(const int* __restrict__ lens) {
    __shared__ int L[B_];
    int i = threadIdx.x;
    L[i] = lens[i];
    __syncthreads();
    int li = L[i];
    int rank = 0;
    for (int j = 0; j < B_; j++) {
        int lj = L[j];
        if (lj > li || (lj == li && j < i)) rank++;
    }
    d_perm[rank]   = i;
    d_lens_s[rank] = li;
}

// ---------------- transpose all weight matrices ----------------
__global__ void transpose_all_kernel(
    const float* __restrict__ wihw, const float* __restrict__ whhw,
    const float* __restrict__ wihp, const float* __restrict__ whhp,
    const float* __restrict__ pinw, const float* __restrict__ fusw,
    const float* __restrict__ h1w)
{
    const float* src; float* dst; int R, K, ld, coff;
    switch (blockIdx.z) {
        case 0: src=wihw; dst=d_WxT;  R=G3_; K=E_;    ld=E_+H_; coff=0;   break;
        case 1: src=wihw; dst=d_WhT;  R=G3_; K=H_;    ld=E_+H_; coff=E_;  break;
        case 2: src=whhw; dst=d_WhhT; R=G3_; K=H_;    ld=H_;    coff=0;   break;
        case 3: src=wihp; dst=d_WipT; R=G3_; K=H_;    ld=H_;    coff=0;   break;
        case 4: src=whhp; dst=d_WhpT; R=G3_; K=H_;    ld=H_;    coff=0;   break;
        case 5: src=pinw; dst=d_pinT; R=H_;  K=H_;    ld=H_;    coff=0;   break;
        case 6: src=fusw; dst=d_fusT; R=H_;  K=2*H_;  ld=2*H_;  coff=0;   break;
        default:src=h1w;  dst=d_h1T;  R=H_;  K=H_;    ld=H_;    coff=0;   break;
    }
    __shared__ float tile[32][33];
    int r0 = blockIdx.y * 32, k0 = blockIdx.x * 32;
    int r = r0 + threadIdx.y, k = k0 + threadIdx.x;
    if (r < R && k < K) tile[threadIdx.y][threadIdx.x] = src[r * ld + coff + k];
    __syncthreads();
    int rr = r0 + threadIdx.x, kk = k0 + threadIdx.y;
    if (rr < R && kk < K) dst[(size_t)kk * R + rr] = tile[threadIdx.x][threadIdx.y];
}

// ============== GEMM v4 cores: split-K, 256 threads (2 halves x 4 warps x 8 rows) ==============
#define ASZ  1024   // floats per A buffer (32k x 32m)
#define BSZ3 3072   // floats per B buffer (32k x 96)
#define BSZ1 1024   // floats per B buffer (32k x 32)
#define SMEM3_BYTES ((4 * ASZ + 4 * BSZ3) * 4)   // 65,536
#define SMEM1_BYTES ((4 * ASZ + 4 * BSZ1) * 4)   // 32,768

__device__ __forceinline__ void gemm3v4(
    const float* __restrict__ A, int lda,
    const float* __restrict__ BT, int K,
    int m0, int u0,
    unsigned long long acc[3][4],
    float* __restrict__ As, float* __restrict__ Bs)
{
    const int tid  = threadIdx.x;
    const int half = tid >> 7;
    const int hid  = tid & 127;
    const int lane = hid & 31;
    const int w4   = hid >> 5;
    const int kbase = half * (K >> 1);
    const int NT   = K >> 6;
    const int am   = lane;
    const int ak   = w4 << 3;
    float* Ash = As + half * 2 * ASZ;
    float* Bsh = Bs + half * 2 * BSZ3;
    const float* Arow = A + (size_t)(m0 + am) * lda + kbase + ak;

    float4 av0 = *(const float4*)(Arow);
    float4 av1 = *(const float4*)(Arow + 4);
    #pragma unroll
    for (int jj = 0; jj < 6; jj++) {
        int e = (hid + (jj << 7)) << 2;
        int k = e / 96, c = e % 96;
        cp16(Bsh + k * 96 + c,
             BT + (size_t)(kbase + k) * G3_ + (c >> 5) * H_ + u0 + (c & 31));
    }
    CP_COMMIT();
    Ash[(ak + 0) * 32 + am] = av0.x; Ash[(ak + 1) * 32 + am] = av0.y;
    Ash[(ak + 2) * 32 + am] = av0.z; Ash[(ak + 3) * 32 + am] = av0.w;
    Ash[(ak + 4) * 32 + am] = av1.x; Ash[(ak + 5) * 32 + am] = av1.y;
    Ash[(ak + 6) * 32 + am] = av1.z; Ash[(ak + 7) * 32 + am] = av1.w;
    if (NT > 1) {
        av0 = *(const float4*)(Arow + 32);
        av1 = *(const float4*)(Arow + 36);
    }
    CP_WAIT0();
    __syncthreads();

    for (int t = 0; t < NT; t++) {
        const int cb = t & 1, nb = (t + 1) & 1;
        if (t + 1 < NT) {
            int k0 = (t + 1) << 5;
            #pragma unroll
            for (int jj = 0; jj < 6; jj++) {
                int e = (hid + (jj << 7)) << 2;
                int k = e / 96, c = e % 96;
                cp16(Bsh + nb * BSZ3 + k * 96 + c,
                     BT + (size_t)(kbase + k0 + k) * G3_ + (c >> 5) * H_ + u0 + (c & 31));
            }
            CP_COMMIT();
            float* d = Ash + nb * ASZ;
            d[(ak + 0) * 32 + am] = av0.x; d[(ak + 1) * 32 + am] = av0.y;
            d[(ak + 2) * 32 + am] = av0.z; d[(ak + 3) * 32 + am] = av0.w;
            d[(ak + 4) * 32 + am] = av1.x; d[(ak + 5) * 32 + am] = av1.y;
            d[(ak + 6) * 32 + am] = av1.z; d[(ak + 7) * 32 + am] = av1.w;
            if (t + 2 < NT) {
                const float* p = Arow + ((t + 2) << 5);
                av0 = *(const float4*)(p);
                av1 = *(const float4*)(p + 4);
            }
        }
        const float* Ab = Ash + cb * ASZ;
        const float* Bb = Bsh + cb * BSZ3;
        #pragma unroll
        for (int k = 0; k < 32; k++) {
            double2 aL = *(const double2*)(Ab + k * 32 + (w4 << 3));
            double2 aH = *(const double2*)(Ab + k * 32 + (w4 << 3) + 4);
            unsigned long long a0 = __double_as_longlong(aL.x);
            unsigned long long a1 = __double_as_longlong(aL.y);
            unsigned long long a2 = __double_as_longlong(aH.x);
            unsigned long long a3 = __double_as_longlong(aH.y);
            unsigned long long br = pack2s(Bb[k * 96 + lane]);
            unsigned long long bz = pack2s(Bb[k * 96 + 32 + lane]);
            unsigned long long bn = pack2s(Bb[k * 96 + 64 + lane]);
            ffma2(acc[0][0], a0, br); ffma2(acc[0][1], a1, br);
            ffma2(acc[0][2], a2, br); ffma2(acc[0][3], a3, br);
            ffma2(acc[1][0], a0, bz); ffma2(acc[1][1], a1, bz);
            ffma2(acc[1][2], a2, bz); ffma2(acc[1][3], a3, bz);
            ffma2(acc[2][0], a0, bn); ffma2(acc[2][1], a1, bn);
            ffma2(acc[2][2], a2, bn); ffma2(acc[2][3], a3, bn);
        }
        CP_WAIT0();
        __syncthreads();
    }
}

__device__ __forceinline__ void gemm1v4(
    const float* __restrict__ A, int lda,
    const float* __restrict__ BT, int ldb, int K,
    int m0, int u0,
    unsigned long long acc[4],
    float* __restrict__ As, float* __restrict__ Bs)
{
    const int tid  = threadIdx.x;
    const int half = tid >> 7;
    const int hid  = tid & 127;
    const int lane = hid & 31;
    const int w4   = hid >> 5;
    const int kbase = half * (K >> 1);
    const int NT   = K >> 6;
    const int am   = lane;
    const int ak   = w4 << 3;
    float* Ash = As + half * 2 * ASZ;
    float* Bsh = Bs + half * 2 * BSZ1;
    const float* Arow = A + (size_t)(m0 + am) * lda + kbase + ak;

    float4 av0 = *(const float4*)(Arow);
    float4 av1 = *(const float4*)(Arow + 4);
    #pragma unroll
    for (int jj = 0; jj < 2; jj++) {
        int e = (hid + (jj << 7)) << 2;
        int k = e >> 5, c = e & 31;
        cp16(Bsh + k * 32 + c, BT + (size_t)(kbase + k) * ldb + u0 + c);
    }
    CP_COMMIT();
    Ash[(ak + 0) * 32 + am] = av0.x; Ash[(ak + 1) * 32 + am] = av0.y;
    Ash[(ak + 2) * 32 + am] = av0.z; Ash[(ak + 3) * 32 + am] = av0.w;
    Ash[(ak + 4) * 32 + am] = av1.x; Ash[(ak + 5) * 32 + am] = av1.y;
    Ash[(ak + 6) * 32 + am] = av1.z; Ash[(ak + 7) * 32 + am] = av1.w;
    if (NT > 1) {
        av0 = *(const float4*)(Arow + 32);
        av1 = *(const float4*)(Arow + 36);
    }
    CP_WAIT0();
    __syncthreads();

    for (int t = 0; t < NT; t++) {
        const int cb = t & 1, nb = (t + 1) & 1;
        if (t + 1 < NT) {
            int k0 = (t + 1) << 5;
            #pragma unroll
            for (int jj = 0; jj < 2; jj++) {
                int e = (hid + (jj << 7)) << 2;
                int k = e >> 5, c = e & 31;
                cp16(Bsh + nb * BSZ1 + k * 32 + c,
                     BT + (size_t)(kbase + k0 + k) * ldb + u0 + c);
            }
            CP_COMMIT();
            float* d = Ash + nb * ASZ;
            d[(ak + 0) * 32 + am] = av0.x; d[(ak + 1) * 32 + am] = av0.y;
            d[(ak + 2) * 32 + am] = av0.z; d[(ak + 3) * 32 + am] = av0.w;
            d[(ak + 4) * 32 + am] = av1.x; d[(ak + 5) * 32 + am] = av1.y;
            d[(ak + 6) * 32 + am] = av1.z; d[(ak + 7) * 32 + am] = av1.w;
            if (t + 2 < NT) {
                const float* p = Arow + ((t + 2) << 5);
                av0 = *(const float4*)(p);
                av1 = *(const float4*)(p + 4);
            }
        }
        const float* Ab = Ash + cb * ASZ;
        const float* Bb = Bsh + cb * BSZ1;
        #pragma unroll
        for (int k = 0; k < 32; k++) {
            double2 aL = *(const double2*)(Ab + k * 32 + (w4 << 3));
            double2 aH = *(const double2*)(Ab + k * 32 + (w4 << 3) + 4);
            unsigned long long bb = pack2s(Bb[k * 32 + lane]);
            ffma2(acc[0], __double_as_longlong(aL.x), bb);
            ffma2(acc[1], __double_as_longlong(aL.y), bb);
            ffma2(acc[2], __double_as_longlong(aH.x), bb);
            ffma2(acc[3], __double_as_longlong(aH.y), bb);
        }
        CP_WAIT0();
        __syncthreads();
    }
}

// merge half-1 accumulators into half-0 (outputs valid for half-0 threads)
__device__ __forceinline__ void reduce3(const unsigned long long acc[3][4],
                                        float o[3][8], float* scratch)
{
    const int tid  = threadIdx.x;
    const int half = tid >> 7;
    const int hid  = tid & 127;
    unsigned long long* red = (unsigned long long*)scratch;
    if (half) {
        #pragma unroll
        for (int g = 0; g < 3; g++)
            #pragma unroll
            for (int p = 0; p < 4; p++)
                red[hid * 12 + g * 4 + p] = acc[g][p];
    }
    __syncthreads();
    if (!half) {
        #pragma unroll
        for (int g = 0; g < 3; g++)
            #pragma unroll
            for (int p = 0; p < 4; p++) {
                float2 a = unpack2(acc[g][p]);
                float2 b = unpack2(red[hid * 12 + g * 4 + p]);
                o[g][2 * p]     = a.x + b.x;
                o[g][2 * p + 1] = a.y + b.y;
            }
    }
    __syncthreads();
}

__device__ __forceinline__ void reduce1(const unsigned long long acc[4],
                                        float o[8], float* scratch)
{
    const int tid  = threadIdx.x;
    const int half = tid >> 7;
    const int hid  = tid & 127;
    unsigned long long* red = (unsigned long long*)scratch;
    if (half) {
        #pragma unroll
        for (int p = 0; p < 4; p++) red[hid * 4 + p] = acc[p];
    }
    __syncthreads();
    if (!half) {
        #pragma unroll
        for (int p = 0; p < 4; p++) {
            float2 a = unpack2(acc[p]);
            float2 b = unpack2(red[hid * 4 + p]);
            o[2 * p]     = a.x + b.x;
            o[2 * p + 1] = a.y + b.y;
        }
    }
    __syncthreads();
}

// ---------------- VW = emb @ Wx^T + b_ih  (whole vocab, once) ----------------
// grid (16, 1000), block 256
__global__ __launch_bounds__(256) void vw_gemm_kernel(
    const float* __restrict__ emb, const float* __restrict__ bihw)
{
    extern __shared__ __align__(16) float smem[];
    float* As = smem;
    float* Bs = smem + 4 * ASZ;
    unsigned long long acc[3][4] = {};
    int u0 = blockIdx.x * 32, m0 = blockIdx.y * 32;
    gemm3v4(emb, E_, d_WxT, E_, m0, u0, acc, As, Bs);
    float g[3][8];
    reduce3(acc, g, Bs);
    if (threadIdx.x >> 7) return;
    int hid = threadIdx.x & 127, lane = hid & 31, w4 = hid >> 5;
    int u = u0 + lane;
    float br = bihw[u], bz = bihw[H_ + u], bn = bihw[2 * H_ + u];
    #pragma unroll
    for (int j = 0; j < 8; j++) {
        size_t m = m0 + (w4 << 3) + j;
        d_VW[m * G3_ + u]          = g[0][j] + br;
        d_VW[m * G3_ + H_ + u]     = g[1][j] + bz;
        d_VW[m * G3_ + 2 * H_ + u] = g[2][j] + bn;
    }
}

// ================= persistent recurrent kernel: whole 512-step loop =================
// grid (16, 8) = 128 blocks, 256 threads, 64KB smem, 1 CTA/SM -> all co-resident.
__global__ __launch_bounds__(256, 1) void recurrent_kernel(
    const int* __restrict__ ids,
    const float* __restrict__ bhh,
    const float* __restrict__ pinb,
    const float* __restrict__ bip,
    const float* __restrict__ bhp)
{
    extern __shared__ __align__(16) float smem[];
    float* As = smem;
    float* Bs = smem + 4 * ASZ;
    const int u0 = blockIdx.x * 32, m0 = blockIdx.y * 32;
    const int tid  = threadIdx.x;
    const int half = tid >> 7;
    const int hid  = tid & 127;
    const int lane = hid & 31;
    const int w4   = hid >> 5;
    const int u = u0 + lane;
    const int blklen = d_lens_s[m0];     // max length in this row-block (sorted desc)

    // hoisted per-block constants
    const float bhr = bhh[u],  bhz = bhh[H_ + u],  bhn = bhh[2 * H_ + u];
    const float pb  = pinb[u];
    const float bir = bip[u],  biz = bip[H_ + u],  bin = bip[2 * H_ + u];
    const float bpr = bhp[u],  bpz = bhp[H_ + u],  bpn = bhp[2 * H_ + u];
    int rowbase[8], rowlen[8];
    #pragma unroll
    for (int j = 0; j < 8; j++) {
        int m = m0 + (w4 << 3) + j;
        rowbase[j] = d_perm[m] * S_;
        rowlen[j]  = d_lens_s[m];
    }

    unsigned tgt = 0;
    for (int t = 0; t < S_; t++) {
        // ---- worker step ----
        if (blklen > t - 2) {
            const float* __restrict__ hwin = d_hw[t & 1];
            float* __restrict__ hwout      = d_hw[(t + 1) & 1];
            unsigned long long acc[3][4] = {};
            gemm3v4(hwin, H_, d_WhhT, H_, m0, u0, acc, As, Bs);
            float g[3][8];
            reduce3(acc, g, Bs);
            if (!half) {
                #pragma unroll
                for (int j = 0; j < 8; j++) {
                    int m  = m0 + (w4 << 3) + j;
                    int id = ids[rowbase[j] + t];
                    const float* vw  = d_VW  + (size_t)id * G3_;
                    const float* hpp = d_HPP + (size_t)m  * G3_;
                    float r = sigf(vw[u] + hpp[u] + g[0][j] + bhr);
                    float z = sigf(vw[H_ + u] + hpp[H_ + u] + g[1][j] + bhz);
                    float n = tanh_fast(vw[2 * H_ + u] + hpp[2 * H_ + u] + r * (g[2][j] + bhn));
                    float hold = hwin[m * H_ + u];
                    hwout[m * H_ + u] = (t < rowlen[j]) ? ((1.0f - z) * n + z * hold) : hold;
                }
            }
        }
        gbar(tgt);

        // ---- planner round every 4 steps ----
        if (((t + 1) & 3) == 0) {
            const bool pact = (blklen > t - 8);
            const int p = ((t + 1) >> 2) - 1;
            const float* __restrict__ hpin = d_hp[p & 1];
            float* __restrict__ hpout      = d_hp[(p + 1) & 1];

            // pi = hw @ pin^T + pin_b
            if (pact) {
                unsigned long long a1[4] = {};
                gemm1v4(d_hw[(t + 1) & 1], H_, d_pinT, H_, H_, m0, u0, a1, As, Bs);
                float a[8];
                reduce1(a1, a, Bs);
                if (!half) {
                    #pragma unroll
                    for (int j = 0; j < 8; j++) {
                        int m = m0 + (w4 << 3) + j;
                        d_pi[m * H_ + u] = a[j] + pb;
                    }
                }
            }
            gbar(tgt);

            // planner GRU
            if (pact) {
                unsigned long long ai[3][4] = {};
                unsigned long long ah[3][4] = {};
                gemm3v4(d_pi, H_, d_WipT, H_, m0, u0, ai, As, Bs);
                gemm3v4(hpin, H_, d_WhpT, H_, m0, u0, ah, As, Bs);
                float gi[3][8], gh[3][8];
                reduce3(ai, gi, Bs);
                reduce3(ah, gh, Bs);
                if (!half) {
                    #pragma unroll
                    for (int j = 0; j < 8; j++) {
                        int m = m0 + (w4 << 3) + j;
                        float r = sigf(gi[0][j] + bir + gh[0][j] + bpr);
                        float z = sigf(gi[1][j] + biz + gh[1][j] + bpz);
                        float n = tanh_fast(gi[2][j] + bin + r * (gh[2][j] + bpn));
                        float hold = hpin[m * H_ + u];
                        hpout[m * H_ + u] = (t < rowlen[j]) ? ((1.0f - z) * n + z * hold) : hold;
                    }
                }
            }
            gbar(tgt);

            // HPP = hp @ WhT
            if (pact) {
                unsigned long long ac[3][4] = {};
                gemm3v4(hpout, H_, d_WhT, H_, m0, u0, ac, As, Bs);
                float g[3][8];
                reduce3(ac, g, Bs);
                if (!half) {
                    #pragma unroll
                    for (int j = 0; j < 8; j++) {
                        size_t m = m0 + (w4 << 3) + j;
                        d_HPP[m * G3_ + u]          = g[0][j];
                        d_HPP[m * G3_ + H_ + u]     = g[1][j];
                        d_HPP[m * G3_ + 2 * H_ + u] = g[2][j];
                    }
                }
            }
            gbar(tgt);
        }
    }
}

// ---------------- fused = tanh([hw,hp] @ fus^T + fus_b) ----------------
__global__ __launch_bounds__(256) void fusion_kernel(const float* __restrict__ fusb)
{
    extern __shared__ __align__(16) float smem[];
    float* As = smem;
    float* Bs = smem + 4 * ASZ;
    int u0 = blockIdx.x * 32, m0 = blockIdx.y * 32;
    unsigned long long acc[4] = {};
    gemm1v4(d_hw[0], H_, d_fusT, H_, H_, m0, u0, acc, As, Bs);
    gemm1v4(d_hp[0], H_, d_fusT + (size_t)H_ * H_, H_, H_, m0, u0, acc, As, Bs);
    float a[8];
    reduce1(acc, a, Bs);
    if (threadIdx.x >> 7) return;
    int hid = threadIdx.x & 127, lane = hid & 31, w4 = hid >> 5;
    int u = u0 + lane;
    float bb = fusb[u];
    #pragma unroll
    for (int j = 0; j < 8; j++) {
        int m = m0 + (w4 << 3) + j;
        d_fused[m * H_ + u] = tanh_fast(a[j] + bb);
    }
}

// ---------------- h = relu(fused @ h1^T + h1_b) ----------------
__global__ __launch_bounds__(256) void h1_kernel(const float* __restrict__ h1b)
{
    extern __shared__ __align__(16) float smem[];
    float* As = smem;
    float* Bs = smem + 4 * ASZ;
    int u0 = blockIdx.x * 32, m0 = blockIdx.y * 32;
    unsigned long long acc[4] = {};
    gemm1v4(d_fused, H_, d_h1T, H_, H_, m0, u0, acc, As, Bs);
    float a[8];
    reduce1(acc, a, Bs);
    if (threadIdx.x >> 7) return;
    int hid = threadIdx.x & 127, lane = hid & 31, w4 = hid >> 5;
    int u = u0 + lane;
    float bb = h1b[u];
    #pragma unroll
    for (int j = 0; j < 8; j++) {
        int m = m0 + (w4 << 3) + j;
        d_relu[m * H_ + u] = fmaxf(a[j] + bb, 0.0f);
    }
}

// ---------------- out = h @ h2^T + h2_b (un-permutes rows) ----------------
__global__ void out_kernel(const float* __restrict__ h2w, const float* __restrict__ h2b,
                           float* __restrict__ out)
{
    int b = blockIdx.x;                 // permuted row
    int c = threadIdx.x >> 5;           // 0..9
    int lane = threadIdx.x & 31;
    float s = 0.0f;
    const float* hrow = d_relu + b * H_;
    const float* wrow = h2w + c * H_;
    for (int k = lane; k < H_; k += 32) s += hrow[k] * wrow[k];
    #pragma unroll
    for (int o = 16; o; o >>= 1) s += __shfl_down_sync(0xffffffff, s, o);
    if (lane == 0) out[d_perm[b] * 10 + c] = s + h2b[c];
}

// ---------------- host launcher (graph-capturable, no allocs) ----------------
extern "C" void kernel_launch(void* const* d_in, const int* in_sizes, int n_in,
                              void* d_out, int out_size)
{
    (void)in_sizes; (void)n_in; (void)out_size;
    const int*   ids  = (const int*)  d_in[0];
    const int*   lens = (const int*)  d_in[1];
    const float* emb  = (const float*)d_in[2];
    const float* wihw = (const float*)d_in[3];
    const float* whhw = (const float*)d_in[4];
    const float* bihw = (const float*)d_in[5];
    const float* bhhw = (const float*)d_in[6];
    const float* pinw = (const float*)d_in[7];
    const float* pinb = (const float*)d_in[8];
    const float* wihp = (const float*)d_in[9];
    const float* whhp = (const float*)d_in[10];
    const float* bihp = (const float*)d_in[11];
    const float* bhhp = (const float*)d_in[12];
    const float* fusw = (const float*)d_in[13];
    const float* fusb = (const float*)d_in[14];
    const float* h1w  = (const float*)d_in[15];
    const float* h1b  = (const float*)d_in[16];
    const float* h2w  = (const float*)d_in[17];
    const float* h2b  = (const float*)d_in[18];
    float* out = (float*)d_out;

    static int attr_done = 0;
    if (!attr_done) {
        cudaFuncSetAttribute(vw_gemm_kernel,   cudaFuncAttributeMaxDynamicSharedMemorySize, SMEM3_BYTES);
        cudaFuncSetAttribute(recurrent_kernel, cudaFuncAttributeMaxDynamicSharedMemorySize, SMEM3_BYTES);
        cudaFuncSetAttribute(fusion_kernel,    cudaFuncAttributeMaxDynamicSharedMemorySize, SMEM1_BYTES);
        cudaFuncSetAttribute(h1_kernel,        cudaFuncAttributeMaxDynamicSharedMemorySize, SMEM1_BYTES);
        attr_done = 1;
    }

    init_zero_kernel<<<(B_ * G3_ + 255) / 256, 256>>>();
    sort_kernel<<<1, B_>>>(lens);
    transpose_all_kernel<<<dim3(32, 48, 8), dim3(32, 32)>>>(
        wihw, whhw, wihp, whhp, pinw, fusw, h1w);
    vw_gemm_kernel<<<dim3(16, VOCAB_ / 32), 256, SMEM3_BYTES>>>(emb, bihw);

    // entire 512-step recurrence in ONE persistent kernel
    recurrent_kernel<<<dim3(16, 8), 256, SMEM3_BYTES>>>(ids, bhhw, pinb, bihp, bhhp);

    fusion_kernel<<<dim3(16, 8), 256, SMEM1_BYTES>>>(fusb);
    h1_kernel<<<dim3(16, 8), 256, SMEM1_BYTES>>>(h1b);
    out_kernel<<<B_, 320>>>(h2w, h2b, out);
}